// round 6
// baseline (speedup 1.0000x reference)
#include <cuda_runtime.h>

#define S_  2048
#define D_  64
#define W_  64
#define NW_ (S_ - W_)   // 1984 windows
#define NT_ 256
#define SLICES_ 4
#define ROWS_PER_CTA_ (S_ / SLICES_)   // 512

// 8 MB scratch for per-row squared L2 norms (static: allocation rules)
__device__ float g_sq[1024 * S_];

// Level offsets for the associative-scan pyramid (sizes 2048,1024,...,1 => 4095 floats)
__device__ __constant__ int OFF_[12] = {0,2048,3072,3584,3840,3968,4032,4064,4080,4088,4092,4094};

// ============================================================================
// Kernel 1: pure streaming row-norm reduce. grid=(SLICES_, B), block=256.
// Bit-exact XLA row-reduction tree (same as the passing fused kernel).
// ============================================================================
__global__ __launch_bounds__(NT_) void swl2_sq_kernel(const float* __restrict__ x)
{
    const int lane = threadIdx.x & 31;
    const int warp = threadIdx.x >> 5;
    const int i8   = lane & 7;     // float4 slot within row
    const int g    = lane >> 3;    // row-in-warp [0,4)
    const int b    = blockIdx.y;

    const float* xrow = x + (size_t)b * S_ * D_;
    float* sqb = g_sq + (size_t)b * S_;
    const int rowBase = blockIdx.x * ROWS_PER_CTA_;

    #pragma unroll 2
    for (int pass = 0; pass < ROWS_PER_CTA_ / 32; ++pass) {  // 16 passes, 4 rows/warp
        const int row = rowBase + pass * 32 + warp * 4 + g;
        const float4* r4 = (const float4*)(xrow + row * D_);
        float4 q0 = r4[i8];
        float4 q1 = r4[i8 + 8];
        // t_{4i+k} = x[4i+k]^2 + x[4i+k+32]^2
        float s0 = __fadd_rn(__fmul_rn(q0.x, q0.x), __fmul_rn(q1.x, q1.x));
        float s1 = __fadd_rn(__fmul_rn(q0.y, q0.y), __fmul_rn(q1.y, q1.y));
        float s2 = __fadd_rn(__fmul_rn(q0.z, q0.z), __fmul_rn(q1.z, q1.z));
        float s3 = __fadd_rn(__fmul_rn(q0.w, q0.w), __fmul_rn(q1.w, q1.w));
        #pragma unroll
        for (int off = 4; off; off >>= 1) {          // t-offsets 16,8,4
            s0 = __fadd_rn(s0, __shfl_xor_sync(0xffffffffu, s0, off));
            s1 = __fadd_rn(s1, __shfl_xor_sync(0xffffffffu, s1, off));
            s2 = __fadd_rn(s2, __shfl_xor_sync(0xffffffffu, s2, off));
            s3 = __fadd_rn(s3, __shfl_xor_sync(0xffffffffu, s3, off));
        }
        const float w0 = __fadd_rn(s0, s2);          // t-offset 2
        const float w1 = __fadd_rn(s1, s3);
        if (i8 == 0) sqb[row] = __fadd_rn(w0, w1);   // t-offset 1
    }
}

// ============================================================================
// Kernel 2: scan + argmax + gather. grid=B, block=256.
// ============================================================================
__global__ __launch_bounds__(NT_) void swl2_pick_kernel(
    const float* __restrict__ x, float* __restrict__ out)
{
    __shared__ float scan[4096];   // level-0 (sq) at [0,2048), pyramid above
    __shared__ float wv[8];
    __shared__ int   wi[8];
    __shared__ int   s_idx;

    const int b    = blockIdx.x;
    const int tid  = threadIdx.x;
    const int lane = tid & 31;
    const int warp = tid >> 5;

    // Load sq row (8 KB) coalesced
    const float4* sq4 = (const float4*)(g_sq + (size_t)b * S_);
    float4* sc4 = (float4*)scan;
    #pragma unroll
    for (int i = 0; i < (S_ / 4) / NT_; ++i)         // 2 float4 per thread
        sc4[i * NT_ + tid] = sq4[i * NT_ + tid];
    __syncthreads();

    // ---- JAX associative_scan cumsum, bit-exact bracketing ----
    #pragma unroll
    for (int k = 0; k < 3; ++k) {                    // down, m=1024,512,256
        const int src = OFF_[k], dst = OFF_[k + 1];
        const int m = 2048 >> (k + 1);
        for (int i = tid; i < m; i += NT_)
            scan[dst + i] = __fadd_rn(scan[src + 2*i], scan[src + 2*i + 1]);
        __syncthreads();
    }
    if (warp == 0) {                                 // middle levels in warp 0
        #pragma unroll
        for (int k = 3; k < 11; ++k) {               // down, m=128..1
            const int src = OFF_[k], dst = OFF_[k + 1];
            const int m = 2048 >> (k + 1);
            for (int i = lane; i < m; i += 32)
                scan[dst + i] = __fadd_rn(scan[src + 2*i], scan[src + 2*i + 1]);
            __syncwarp();
        }
        #pragma unroll
        for (int k = 10; k >= 3; --k) {              // up, m=1..128
            const int ok = OFF_[k], ok1 = OFF_[k + 1];
            const int m = 2048 >> (k + 1);
            for (int i = lane; i < m; i += 32) {
                const float so = scan[ok1 + i];
                if (i > 0)
                    scan[ok + 2*i] = __fadd_rn(scan[ok1 + i - 1], scan[ok + 2*i]);
                scan[ok + 2*i + 1] = so;
            }
            __syncwarp();
        }
    }
    __syncthreads();
    #pragma unroll
    for (int k = 2; k >= 0; --k) {                   // up, m=256,512,1024
        const int ok = OFF_[k], ok1 = OFF_[k + 1];
        const int m = 2048 >> (k + 1);
        for (int i = tid; i < m; i += NT_) {
            const float so = scan[ok1 + i];
            if (i > 0)
                scan[ok + 2*i] = __fadd_rn(scan[ok1 + i - 1], scan[ok + 2*i]);
            scan[ok + 2*i + 1] = so;
        }
        __syncthreads();
    }
    // scan[0..2047] = cumsum(sq) with JAX's exact fp32 rounding.

    // ---- win[j] = c[j+64] - c[j]; local argmax over 8 windows/thread ----
    float best = -3.402823466e+38f;
    int   bidx = 0x7fffffff;
    const int j0 = tid * 8;
    if (j0 < NW_) {                                  // threads 0..247 active
        #pragma unroll
        for (int jj = j0; jj < j0 + 8; ++jj) {
            const float cl = (jj == 0) ? 0.0f : scan[jj - 1];
            const float w  = __fadd_rn(scan[jj + W_ - 1], -cl);
            if (w > best) { best = w; bidx = jj; }   // strict > => first occurrence
        }
    }

    // ---- block argmax (max value, min index on exact ties) ----
    #pragma unroll
    for (int off = 16; off; off >>= 1) {
        float ov = __shfl_xor_sync(0xffffffffu, best, off);
        int   oi = __shfl_xor_sync(0xffffffffu, bidx, off);
        if (ov > best || (ov == best && oi < bidx)) { best = ov; bidx = oi; }
    }
    if (lane == 0) { wv[warp] = best; wi[warp] = bidx; }
    __syncthreads();
    if (tid == 0) {
        float bv = wv[0]; int bi = wi[0];
        #pragma unroll
        for (int i = 1; i < 8; ++i)
            if (wv[i] > bv || (wv[i] == bv && wi[i] < bi)) { bv = wv[i]; bi = wi[i]; }
        s_idx = bi;
    }
    __syncthreads();

    // ---- gather 64 rows (16 KB) to output, coalesced float4 ----
    const float* xrow = x + (size_t)b * S_ * D_;
    const int idx = s_idx;
    const float4* src = (const float4*)(xrow + (size_t)idx * D_);
    float4* dst = (float4*)(out + (size_t)b * W_ * D_);
    #pragma unroll
    for (int i = 0; i < (W_ * 16) / NT_; ++i)        // 4 float4 per thread
        dst[i * NT_ + tid] = src[i * NT_ + tid];
}

extern "C" void kernel_launch(void* const* d_in, const int* in_sizes, int n_in,
                              void* d_out, int out_size)
{
    const float* x = (const float*)d_in[0];
    float* out = (float*)d_out;
    const int B = in_sizes[0] / (S_ * D_);   // 1024 for this problem
    dim3 g1(SLICES_, B);
    swl2_sq_kernel<<<g1, NT_>>>(x);
    swl2_pick_kernel<<<B, NT_>>>(x, out);
}

// round 7
// speedup vs baseline: 1.0323x; 1.0323x over previous
#include <cuda_runtime.h>

#define S_  2048
#define D_  64
#define W_  64
#define NW_ (S_ - W_)   // 1984 windows
#define NT_ 256

// Level offsets for the associative-scan pyramid (sizes 2048,1024,...,1 => 4095 floats)
__device__ __constant__ int OFF_[12] = {0,2048,3072,3584,3840,3968,4032,4064,4080,4088,4092,4094};

__global__ __launch_bounds__(NT_) void swl2_pool_kernel(
    const float* __restrict__ x, float* __restrict__ out)
{
    __shared__ float scan[4096];   // level-0 (sq) at [0,2048), pyramid above
    __shared__ float wv[8];
    __shared__ int   wi[8];
    __shared__ int   s_idx;

    const int b    = blockIdx.x;
    const int tid  = threadIdx.x;
    const int lane = tid & 31;
    const int warp = tid >> 5;
    const int i8   = lane & 7;     // float4 slot within row
    const int g    = lane >> 3;    // row-in-warp [0,4)

    const float* xrow = x + (size_t)b * S_ * D_;

    // ---- Phase A: sq[r] = sum(x[r]^2), bit-exact XLA tree, float4 loads ----
    // t_{4i+k} = row[4i+k]^2 + row[4i+k+32]^2 from q0=row4[i], q1=row4[i+8].
    // Butterfly offsets 16,8,4 in t-space == lane-xor 4,2,1 (elementwise, 4 slots);
    // offsets 2,1 are in-lane. All-lane xor butterflies are bit-identical to
    // the reference lane-0 bracketing (FADD commutes bitwise).
    #pragma unroll 4
    for (int pass = 0; pass < S_ / 32; ++pass) {     // 64 passes, 4 rows/warp
        const int row = pass * 32 + warp * 4 + g;
        const float4* r4 = (const float4*)(xrow + row * D_);
        float4 q0 = r4[i8];
        float4 q1 = r4[i8 + 8];
        float s0 = __fadd_rn(__fmul_rn(q0.x, q0.x), __fmul_rn(q1.x, q1.x));
        float s1 = __fadd_rn(__fmul_rn(q0.y, q0.y), __fmul_rn(q1.y, q1.y));
        float s2 = __fadd_rn(__fmul_rn(q0.z, q0.z), __fmul_rn(q1.z, q1.z));
        float s3 = __fadd_rn(__fmul_rn(q0.w, q0.w), __fmul_rn(q1.w, q1.w));
        #pragma unroll
        for (int off = 4; off; off >>= 1) {          // t-offsets 16,8,4
            s0 = __fadd_rn(s0, __shfl_xor_sync(0xffffffffu, s0, off));
            s1 = __fadd_rn(s1, __shfl_xor_sync(0xffffffffu, s1, off));
            s2 = __fadd_rn(s2, __shfl_xor_sync(0xffffffffu, s2, off));
            s3 = __fadd_rn(s3, __shfl_xor_sync(0xffffffffu, s3, off));
        }
        // t-offset 2: (0,2),(1,3); t-offset 1: final
        const float w0 = __fadd_rn(s0, s2);
        const float w1 = __fadd_rn(s1, s3);
        if (i8 == 0) scan[row] = __fadd_rn(w0, w1);
    }
    __syncthreads();

    // ---- Phase B: JAX associative_scan cumsum, bit-exact bracketing ----
    // Down-sweep block levels k=0..2 (m=1024,512,256)
    #pragma unroll
    for (int k = 0; k < 3; ++k) {
        const int src = OFF_[k], dst = OFF_[k + 1];
        const int m = 2048 >> (k + 1);
        for (int i = tid; i < m; i += NT_)
            scan[dst + i] = __fadd_rn(scan[src + 2*i], scan[src + 2*i + 1]);
        __syncthreads();
    }
    // Levels k=3..10 down + k=10..3 up in warp 0 only (syncwarp between levels)
    if (warp == 0) {
        #pragma unroll
        for (int k = 3; k < 11; ++k) {               // down, m=128..1
            const int src = OFF_[k], dst = OFF_[k + 1];
            const int m = 2048 >> (k + 1);
            for (int i = lane; i < m; i += 32)
                scan[dst + i] = __fadd_rn(scan[src + 2*i], scan[src + 2*i + 1]);
            __syncwarp();
        }
        #pragma unroll
        for (int k = 10; k >= 3; --k) {              // up, m=1..128
            const int ok = OFF_[k], ok1 = OFF_[k + 1];
            const int m = 2048 >> (k + 1);
            for (int i = lane; i < m; i += 32) {
                const float so = scan[ok1 + i];
                if (i > 0)
                    scan[ok + 2*i] = __fadd_rn(scan[ok1 + i - 1], scan[ok + 2*i]);
                scan[ok + 2*i + 1] = so;
            }
            __syncwarp();
        }
    }
    __syncthreads();
    // Up-sweep block levels k=2..0
    #pragma unroll
    for (int k = 2; k >= 0; --k) {
        const int ok = OFF_[k], ok1 = OFF_[k + 1];
        const int m = 2048 >> (k + 1);
        for (int i = tid; i < m; i += NT_) {
            const float so = scan[ok1 + i];
            if (i > 0)
                scan[ok + 2*i] = __fadd_rn(scan[ok1 + i - 1], scan[ok + 2*i]);
            scan[ok + 2*i + 1] = so;
        }
        __syncthreads();
    }
    // Now scan[0..2047] = cumsum(sq) with JAX's exact fp32 rounding.

    // ---- Phase C: win[j] = c[j+64] - c[j]; local argmax over 8 windows/thread ----
    float best = -3.402823466e+38f;
    int   bidx = 0x7fffffff;
    const int j0 = tid * 8;
    if (j0 < NW_) {                                  // threads 0..247 active
        #pragma unroll
        for (int jj = j0; jj < j0 + 8; ++jj) {
            const float cl = (jj == 0) ? 0.0f : scan[jj - 1];
            const float w  = __fadd_rn(scan[jj + W_ - 1], -cl);
            if (w > best) { best = w; bidx = jj; }   // strict > => first occurrence
        }
    }

    // ---- Phase D: block argmax (max value, min index on exact ties) ----
    #pragma unroll
    for (int off = 16; off; off >>= 1) {
        float ov = __shfl_xor_sync(0xffffffffu, best, off);
        int   oi = __shfl_xor_sync(0xffffffffu, bidx, off);
        if (ov > best || (ov == best && oi < bidx)) { best = ov; bidx = oi; }
    }
    if (lane == 0) { wv[warp] = best; wi[warp] = bidx; }
    __syncthreads();
    if (tid == 0) {
        float bv = wv[0]; int bi = wi[0];
        #pragma unroll
        for (int i = 1; i < 8; ++i)
            if (wv[i] > bv || (wv[i] == bv && wi[i] < bi)) { bv = wv[i]; bi = wi[i]; }
        s_idx = bi;
    }
    __syncthreads();

    // ---- Phase E: gather 64 rows (16 KB) to output, coalesced float4 ----
    const int idx = s_idx;
    const float4* src = (const float4*)(xrow + (size_t)idx * D_);
    float4* dst = (float4*)(out + (size_t)b * W_ * D_);
    #pragma unroll
    for (int i = 0; i < (W_ * 16) / NT_; ++i)        // 4 float4 per thread
        dst[i * NT_ + tid] = src[i * NT_ + tid];
}

extern "C" void kernel_launch(void* const* d_in, const int* in_sizes, int n_in,
                              void* d_out, int out_size)
{
    const float* x = (const float*)d_in[0];
    float* out = (float*)d_out;
    const int B = in_sizes[0] / (S_ * D_);   // 1024 for this problem
    swl2_pool_kernel<<<B, NT_>>>(x, out);
}

// round 8
// speedup vs baseline: 1.1352x; 1.0997x over previous
#include <cuda_runtime.h>

#define S_  2048
#define D_  64
#define W_  64
#define NW_ (S_ - W_)   // 1984 windows
#define NT_ 256

// Level offsets for the associative-scan pyramid (sizes 2048,1024,...,1 => 4095 floats)
__device__ __constant__ int OFF_[12] = {0,2048,3072,3584,3840,3968,4032,4064,4080,4088,4092,4094};

__global__ __launch_bounds__(NT_) void swl2_pool_kernel(
    const float* __restrict__ x, float* __restrict__ out)
{
    __shared__ float scan[4096];   // level-0 (sq) at [0,2048), pyramid above
    __shared__ float wv[8];
    __shared__ int   wi[8];
    __shared__ int   s_idx;

    const int b    = blockIdx.x;
    const int tid  = threadIdx.x;
    const int lane = tid & 31;
    const int warp = tid >> 5;
    const int i8   = lane & 7;     // float4 slot within row
    const int g    = lane >> 3;    // row-in-warp [0,4)

    const float* xrow = x + (size_t)b * S_ * D_;

    // ---- Phase A: sq[r] = sum(x[r]^2), bit-exact XLA tree, float4 loads ----
    // Streaming loads use __ldcs (evict-first): data is read once here; keeps
    // L2 free for the Phase E gather re-read. Rounding identical.
    // t_{4i+k} = row[4i+k]^2 + row[4i+k+32]^2 from q0=row4[i], q1=row4[i+8].
    // Butterfly offsets 16,8,4 in t-space == lane-xor 4,2,1 (elementwise);
    // offsets 2,1 in-lane. Bit-identical to reference lane-0 bracketing.
    #pragma unroll 4
    for (int pass = 0; pass < S_ / 32; ++pass) {     // 64 passes, 4 rows/warp
        const int row = pass * 32 + warp * 4 + g;
        const float4* r4 = (const float4*)(xrow + row * D_);
        float4 q0 = __ldcs(r4 + i8);
        float4 q1 = __ldcs(r4 + i8 + 8);
        float s0 = __fadd_rn(__fmul_rn(q0.x, q0.x), __fmul_rn(q1.x, q1.x));
        float s1 = __fadd_rn(__fmul_rn(q0.y, q0.y), __fmul_rn(q1.y, q1.y));
        float s2 = __fadd_rn(__fmul_rn(q0.z, q0.z), __fmul_rn(q1.z, q1.z));
        float s3 = __fadd_rn(__fmul_rn(q0.w, q0.w), __fmul_rn(q1.w, q1.w));
        #pragma unroll
        for (int off = 4; off; off >>= 1) {          // t-offsets 16,8,4
            s0 = __fadd_rn(s0, __shfl_xor_sync(0xffffffffu, s0, off));
            s1 = __fadd_rn(s1, __shfl_xor_sync(0xffffffffu, s1, off));
            s2 = __fadd_rn(s2, __shfl_xor_sync(0xffffffffu, s2, off));
            s3 = __fadd_rn(s3, __shfl_xor_sync(0xffffffffu, s3, off));
        }
        // t-offset 2: (0,2),(1,3); t-offset 1: final
        const float w0 = __fadd_rn(s0, s2);
        const float w1 = __fadd_rn(s1, s3);
        if (i8 == 0) scan[row] = __fadd_rn(w0, w1);
    }
    __syncthreads();

    // ---- Phase B: JAX associative_scan cumsum, bit-exact bracketing ----
    // Down-sweep block levels k=0..2 (m=1024,512,256)
    #pragma unroll
    for (int k = 0; k < 3; ++k) {
        const int src = OFF_[k], dst = OFF_[k + 1];
        const int m = 2048 >> (k + 1);
        for (int i = tid; i < m; i += NT_)
            scan[dst + i] = __fadd_rn(scan[src + 2*i], scan[src + 2*i + 1]);
        __syncthreads();
    }
    // Levels k=3..10 down + k=10..3 up in warp 0 only (syncwarp between levels)
    if (warp == 0) {
        #pragma unroll
        for (int k = 3; k < 11; ++k) {               // down, m=128..1
            const int src = OFF_[k], dst = OFF_[k + 1];
            const int m = 2048 >> (k + 1);
            for (int i = lane; i < m; i += 32)
                scan[dst + i] = __fadd_rn(scan[src + 2*i], scan[src + 2*i + 1]);
            __syncwarp();
        }
        #pragma unroll
        for (int k = 10; k >= 3; --k) {              // up, m=1..128
            const int ok = OFF_[k], ok1 = OFF_[k + 1];
            const int m = 2048 >> (k + 1);
            for (int i = lane; i < m; i += 32) {
                const float so = scan[ok1 + i];
                if (i > 0)
                    scan[ok + 2*i] = __fadd_rn(scan[ok1 + i - 1], scan[ok + 2*i]);
                scan[ok + 2*i + 1] = so;
            }
            __syncwarp();
        }
    }
    __syncthreads();
    // Up-sweep block levels k=2..0
    #pragma unroll
    for (int k = 2; k >= 0; --k) {
        const int ok = OFF_[k], ok1 = OFF_[k + 1];
        const int m = 2048 >> (k + 1);
        for (int i = tid; i < m; i += NT_) {
            const float so = scan[ok1 + i];
            if (i > 0)
                scan[ok + 2*i] = __fadd_rn(scan[ok1 + i - 1], scan[ok + 2*i]);
            scan[ok + 2*i + 1] = so;
        }
        __syncthreads();
    }
    // Now scan[0..2047] = cumsum(sq) with JAX's exact fp32 rounding.

    // ---- Phase C: win[j] = c[j+64] - c[j]; local argmax over 8 windows/thread ----
    float best = -3.402823466e+38f;
    int   bidx = 0x7fffffff;
    const int j0 = tid * 8;
    if (j0 < NW_) {                                  // threads 0..247 active
        #pragma unroll
        for (int jj = j0; jj < j0 + 8; ++jj) {
            const float cl = (jj == 0) ? 0.0f : scan[jj - 1];
            const float w  = __fadd_rn(scan[jj + W_ - 1], -cl);
            if (w > best) { best = w; bidx = jj; }   // strict > => first occurrence
        }
    }

    // ---- Phase D: block argmax (max value, min index on exact ties) ----
    #pragma unroll
    for (int off = 16; off; off >>= 1) {
        float ov = __shfl_xor_sync(0xffffffffu, best, off);
        int   oi = __shfl_xor_sync(0xffffffffu, bidx, off);
        if (ov > best || (ov == best && oi < bidx)) { best = ov; bidx = oi; }
    }
    if (lane == 0) { wv[warp] = best; wi[warp] = bidx; }
    __syncthreads();
    if (tid == 0) {
        float bv = wv[0]; int bi = wi[0];
        #pragma unroll
        for (int i = 1; i < 8; ++i)
            if (wv[i] > bv || (wv[i] == bv && wi[i] < bi)) { bv = wv[i]; bi = wi[i]; }
        s_idx = bi;
    }
    __syncthreads();

    // ---- Phase E: gather 64 rows (16 KB) to output, coalesced float4 ----
    const int idx = s_idx;
    const float4* src = (const float4*)(xrow + (size_t)idx * D_);
    float4* dst = (float4*)(out + (size_t)b * W_ * D_);
    #pragma unroll
    for (int i = 0; i < (W_ * 16) / NT_; ++i)        // 4 float4 per thread
        dst[i * NT_ + tid] = src[i * NT_ + tid];
}

extern "C" void kernel_launch(void* const* d_in, const int* in_sizes, int n_in,
                              void* d_out, int out_size)
{
    const float* x = (const float*)d_in[0];
    float* out = (float*)d_out;
    const int B = in_sizes[0] / (S_ * D_);   // 1024 for this problem
    swl2_pool_kernel<<<B, NT_>>>(x, out);
}